// round 1
// baseline (speedup 1.0000x reference)
#include <cuda_runtime.h>
#include <math.h>

// ChannelAttention fused kernel for GB300 (sm_103a).
// Shapes (fixed by the problem):
//   x  : [B=8, O=8, S=32, C=64, H=32, W=32]  fp32   (512 MB)
//   w1 : [O=8, HID=64, C=64]                 fp32   (128 KB)
//   w2 : [O=8, C=64, HID=64]                 fp32   (128 KB)
//   out: [B, O, S, C, 1, 1]                  fp32   (0.5 MB)
//
// One CTA per (b,o,s): pools 64 channels x 1024 spatial values (mean + max),
// then runs the grouped MLP: sigmoid( relu(pm@W1^T)@W2^T + relu(px@W1^T)@W2^T ).

#define C_DIM   64
#define HW_DIM  1024
#define O_DIM   8
#define S_DIM   32
#define THREADS 512

__global__ __launch_bounds__(THREADS, 4)
void channel_attention_kernel(const float* __restrict__ x,
                              const float* __restrict__ w1,
                              const float* __restrict__ w2,
                              float* __restrict__ out)
{
    const int blk = blockIdx.x;                 // b*O*S + o*S + s
    const int o   = (blk / S_DIM) % O_DIM;

    __shared__ float pm[C_DIM];   // pooled mean
    __shared__ float px[C_DIM];   // pooled max
    __shared__ float hs[C_DIM];   // relu(pm@W1) + relu(px@W1) summed

    const int tid  = threadIdx.x;
    const int lane = tid & 31;
    const int wid  = tid >> 5;                  // 16 warps

    const float* base = x + (size_t)blk * (C_DIM * HW_DIM);

    // ---- Phase 1: pooling. One warp handles 4 channels. ----
    #pragma unroll
    for (int i = 0; i < 4; ++i) {
        const int c = wid * 4 + i;
        const float4* row = reinterpret_cast<const float4*>(base + c * HW_DIM);
        float s = 0.0f;
        float m = -INFINITY;
        #pragma unroll
        for (int j = 0; j < 8; ++j) {
            float4 v = row[lane + j * 32];      // coalesced 512B per warp-iter
            s += (v.x + v.y) + (v.z + v.w);
            m = fmaxf(m, fmaxf(fmaxf(v.x, v.y), fmaxf(v.z, v.w)));
        }
        #pragma unroll
        for (int off = 16; off > 0; off >>= 1) {
            s += __shfl_xor_sync(0xFFFFFFFFu, s, off);
            m = fmaxf(m, __shfl_xor_sync(0xFFFFFFFFu, m, off));
        }
        if (lane == 0) {
            pm[c] = s * (1.0f / (float)HW_DIM);
            px[c] = m;
        }
    }
    __syncthreads();

    // ---- Phase 2: FC1 + relu. Thread tid<64 computes hidden unit tid. ----
    if (tid < C_DIM) {
        const float* w1r = w1 + ((size_t)o * C_DIM + tid) * C_DIM;  // W1[o, tid, :]
        float am = 0.0f, ax = 0.0f;
        #pragma unroll
        for (int c = 0; c < C_DIM; ++c) {
            float w = w1r[c];
            am = fmaf(pm[c], w, am);
            ax = fmaf(px[c], w, ax);
        }
        hs[tid] = fmaxf(am, 0.0f) + fmaxf(ax, 0.0f);   // relu(mean)+relu(max)
    }
    __syncthreads();

    // ---- Phase 3: FC2 + sigmoid. Linear => single pass over summed hidden. ----
    if (tid < C_DIM) {
        const float* w2r = w2 + ((size_t)o * C_DIM + tid) * C_DIM;  // W2[o, tid, :]
        float a = 0.0f;
        #pragma unroll
        for (int h = 0; h < C_DIM; ++h)
            a = fmaf(hs[h], w2r[h], a);
        out[(size_t)blk * C_DIM + tid] = 1.0f / (1.0f + __expf(-a));
    }
}

extern "C" void kernel_launch(void* const* d_in, const int* in_sizes, int n_in,
                              void* d_out, int out_size)
{
    const float* x  = (const float*)d_in[0];
    const float* w1 = (const float*)d_in[1];
    const float* w2 = (const float*)d_in[2];
    float* out = (float*)d_out;

    // grid = B*O*S = 8*8*32 = 2048 CTAs
    channel_attention_kernel<<<2048, THREADS>>>(x, w1, w2, out);
}

// round 2
// speedup vs baseline: 1.2353x; 1.2353x over previous
#include <cuda_runtime.h>
#include <math.h>

// ChannelAttention fused kernel for GB300 (sm_103a) — R2.
// Shapes (fixed):
//   x  : [B=8, O=8, S=32, C=64, H=32, W=32]  fp32   (512 MB streamed once)
//   w1 : [O=8, 64, 64], w2 : [O=8, 64, 64]   fp32   (L2-resident)
//   out: [B, O, S, C]                        fp32
//
// One CTA per (b,o,s). 16 warps; each warp pools 4 channels IN PARALLEL
// (4 independent float4 load chains per step -> high MLP to hide DRAM lat).
// __launch_bounds__(512, 2) gives 64 regs/thread so ptxas can front-batch loads.

#define C_DIM   64
#define HW_DIM  1024
#define O_DIM   8
#define S_DIM   32
#define THREADS 512

__global__ __launch_bounds__(THREADS, 2)
void channel_attention_kernel(const float* __restrict__ x,
                              const float* __restrict__ w1,
                              const float* __restrict__ w2,
                              float* __restrict__ out)
{
    const int blk = blockIdx.x;                 // b*O*S + o*S + s
    const int o   = (blk / S_DIM) % O_DIM;

    __shared__ float pm[C_DIM];   // pooled mean
    __shared__ float px[C_DIM];   // pooled max
    __shared__ float hs[C_DIM];   // relu(pm@W1) + relu(px@W1)

    const int tid  = threadIdx.x;
    const int lane = tid & 31;
    const int wid  = tid >> 5;                  // 16 warps

    const float* base = x + (size_t)blk * (C_DIM * HW_DIM);

    // ---- Phase 1: pooling. Each warp handles channels [wid*4, wid*4+4)
    // processed in PARALLEL: 4 independent load chains per j-step.
    const float4* row0 = reinterpret_cast<const float4*>(base + (wid * 4 + 0) * HW_DIM) + lane;
    const float4* row1 = reinterpret_cast<const float4*>(base + (wid * 4 + 1) * HW_DIM) + lane;
    const float4* row2 = reinterpret_cast<const float4*>(base + (wid * 4 + 2) * HW_DIM) + lane;
    const float4* row3 = reinterpret_cast<const float4*>(base + (wid * 4 + 3) * HW_DIM) + lane;

    float s0 = 0.f, s1 = 0.f, s2 = 0.f, s3 = 0.f;
    float m0 = -INFINITY, m1 = -INFINITY, m2 = -INFINITY, m3 = -INFINITY;

    #pragma unroll
    for (int j = 0; j < 8; ++j) {
        float4 v0 = __ldcs(row0 + j * 32);   // streaming: touched once
        float4 v1 = __ldcs(row1 + j * 32);
        float4 v2 = __ldcs(row2 + j * 32);
        float4 v3 = __ldcs(row3 + j * 32);

        s0 += (v0.x + v0.y) + (v0.z + v0.w);
        m0 = fmaxf(m0, fmaxf(fmaxf(v0.x, v0.y), fmaxf(v0.z, v0.w)));
        s1 += (v1.x + v1.y) + (v1.z + v1.w);
        m1 = fmaxf(m1, fmaxf(fmaxf(v1.x, v1.y), fmaxf(v1.z, v1.w)));
        s2 += (v2.x + v2.y) + (v2.z + v2.w);
        m2 = fmaxf(m2, fmaxf(fmaxf(v2.x, v2.y), fmaxf(v2.z, v2.w)));
        s3 += (v3.x + v3.y) + (v3.z + v3.w);
        m3 = fmaxf(m3, fmaxf(fmaxf(v3.x, v3.y), fmaxf(v3.z, v3.w)));
    }

    #pragma unroll
    for (int off = 16; off > 0; off >>= 1) {
        s0 += __shfl_xor_sync(0xFFFFFFFFu, s0, off);
        m0 = fmaxf(m0, __shfl_xor_sync(0xFFFFFFFFu, m0, off));
        s1 += __shfl_xor_sync(0xFFFFFFFFu, s1, off);
        m1 = fmaxf(m1, __shfl_xor_sync(0xFFFFFFFFu, m1, off));
        s2 += __shfl_xor_sync(0xFFFFFFFFu, s2, off);
        m2 = fmaxf(m2, __shfl_xor_sync(0xFFFFFFFFu, m2, off));
        s3 += __shfl_xor_sync(0xFFFFFFFFu, s3, off);
        m3 = fmaxf(m3, __shfl_xor_sync(0xFFFFFFFFu, m3, off));
    }
    if (lane == 0) {
        const int c = wid * 4;
        pm[c + 0] = s0 * (1.0f / (float)HW_DIM);  px[c + 0] = m0;
        pm[c + 1] = s1 * (1.0f / (float)HW_DIM);  px[c + 1] = m1;
        pm[c + 2] = s2 * (1.0f / (float)HW_DIM);  px[c + 2] = m2;
        pm[c + 3] = s3 * (1.0f / (float)HW_DIM);  px[c + 3] = m3;
    }
    __syncthreads();

    // ---- Phase 2: FC1 + relu. Thread tid<64 computes hidden unit tid.
    if (tid < C_DIM) {
        const float* w1r = w1 + ((size_t)o * C_DIM + tid) * C_DIM;  // W1[o, tid, :]
        float am = 0.0f, ax = 0.0f;
        #pragma unroll
        for (int c = 0; c < C_DIM; ++c) {
            float w = __ldg(w1r + c);
            am = fmaf(pm[c], w, am);
            ax = fmaf(px[c], w, ax);
        }
        hs[tid] = fmaxf(am, 0.0f) + fmaxf(ax, 0.0f);
    }
    __syncthreads();

    // ---- Phase 3: FC2 + sigmoid (linear => one pass over summed hidden).
    if (tid < C_DIM) {
        const float* w2r = w2 + ((size_t)o * C_DIM + tid) * C_DIM;  // W2[o, tid, :]
        float a = 0.0f;
        #pragma unroll
        for (int h = 0; h < C_DIM; ++h)
            a = fmaf(hs[h], __ldg(w2r + h), a);
        out[(size_t)blk * C_DIM + tid] = 1.0f / (1.0f + __expf(-a));
    }
}

extern "C" void kernel_launch(void* const* d_in, const int* in_sizes, int n_in,
                              void* d_out, int out_size)
{
    const float* x  = (const float*)d_in[0];
    const float* w1 = (const float*)d_in[1];
    const float* w2 = (const float*)d_in[2];
    float* out = (float*)d_out;

    channel_attention_kernel<<<2048, THREADS>>>(x, w1, w2, out);
}